// round 2
// baseline (speedup 1.0000x reference)
#include <cuda_runtime.h>
#include <cuda_bf16.h>
#include <math.h>

// Monomial layout constants (D = 64, degrees 0..4)
//   off0=0 (1), off1=1 (64), off2=65 (2080), off3=2145 (45760), off4=47905 (766480)
// Total F = 814385.
#define NT 256
#define N_M4_TASKS 2080          // one task per leading (i,j) pair, i<=j
#define N_TASKS (N_M4_TASKS + 64 + 1 + 1)   // + deg3 per-i + deg2 + deg1 = 2146

__device__ float g_partials[N_TASKS];
__device__ int   g_count = 0;

__device__ __forceinline__ int C2i(int n) { return (n >= 2) ? n * (n - 1) / 2 : 0; }
__device__ __forceinline__ int C3i(int n) { return (n >= 3) ? n * (n - 1) * (n - 2) / 6 : 0; }
__device__ __forceinline__ int C4i(int n) { return (n >= 4) ? n * (n - 1) * (n - 2) * (n - 3) / 24 : 0; }

// Unrank flat index p in a triangle with row sizes n, n-1, ..., 1.
// S(r) = r*n - r*(r-1)/2 is the start of row r.
__device__ __forceinline__ void unrank_tri(int n, int p, int& r_out, int& c_out) {
    float b = 2.0f * (float)n + 1.0f;
    float disc = b * b - 8.0f * (float)p;
    int r = (int)(0.5f * (b - sqrtf(disc)));
    if (r < 0) r = 0;
    if (r > n - 1) r = n - 1;
    while (r + 1 <= n - 1 && ((r + 1) * n - (r + 1) * r / 2) <= p) r++;
    while (r > 0 && (r * n - r * (r - 1) / 2) > p) r--;
    r_out = r;
    c_out = p - (r * n - r * (r - 1) / 2);
}

__device__ __forceinline__ float warp_reduce(float v) {
    #pragma unroll
    for (int off = 16; off > 0; off >>= 1)
        v += __shfl_down_sync(0xFFFFFFFFu, v, off);
    return v;
}

__global__ void __launch_bounds__(NT)
poly_fused_kernel(const float* __restrict__ x,
                  const float* __restrict__ w,
                  const float* __restrict__ alphas,
                  float* __restrict__ out) {
    __shared__ float sx[64];
    __shared__ float wsum[NT / 32];
    __shared__ int   s_last;
    const int tid  = threadIdx.x;
    const int lane = tid & 31;
    const int wid  = tid >> 5;
    if (tid < 64) sx[tid] = x[tid];
    __syncthreads();

    const int task = blockIdx.x;
    float acc = 0.0f;
    float scale = 0.0f;

    if (task < N_M4_TASKS) {
        // ---- degree 4: task -> leading pair (i, j), i <= j ----
        int i = 0;
        while (i < 63 && (2080 - C2i(64 - i)) <= task) i++;
        const int j = i + (task - (2080 - C2i(65 - i)));
        const int base = 47905 + (C4i(67) - C4i(67 - i)) + (C3i(66 - i) - C3i(66 - j));
        const int n = 64 - j;                 // inner triangle over (k, l), j<=k<=l<64
        const int count = n * (n + 1) / 2;    // contiguous in w -> coalesced
        scale = alphas[4] * sx[i] * sx[j];
        for (int p = tid; p < count; p += NT) {
            int r, c;
            unrank_tri(n, p, r, c);
            const int k = j + r;
            const int l = k + c;
            acc += w[base + p] * sx[k] * sx[l];
        }
    } else if (task < N_M4_TASKS + 64) {
        // ---- degree 3: task -> leading index i ----
        const int i = task - N_M4_TASKS;
        const int base = 2145 + (C3i(66) - C3i(66 - i));
        const int n = 64 - i;
        const int count = n * (n + 1) / 2;
        scale = alphas[3] * sx[i];
        for (int p = tid; p < count; p += NT) {
            int r, c;
            unrank_tri(n, p, r, c);
            const int jj = i + r;
            const int k = jj + c;
            acc += w[base + p] * sx[jj] * sx[k];
        }
    } else if (task == N_M4_TASKS + 64) {
        // ---- degree 2: full triangle over (i, j) ----
        scale = alphas[2];
        for (int p = tid; p < 2080; p += NT) {
            int r, c;
            unrank_tri(64, p, r, c);
            acc += w[65 + p] * sx[r] * sx[r + c];
        }
    } else {
        // ---- degree 1 ----
        scale = alphas[1];
        if (tid < 64) acc = w[1 + tid] * sx[tid];
    }

    // deterministic reduction: warp shuffle + single shared step
    acc = warp_reduce(acc);
    if (lane == 0) wsum[wid] = acc;
    __syncthreads();
    if (wid == 0) {
        float v = (lane < NT / 32) ? wsum[lane] : 0.0f;
        #pragma unroll
        for (int off = (NT / 32) / 2; off > 0; off >>= 1)
            v += __shfl_down_sync(0xFFFFFFFFu, v, off);
        if (lane == 0) {
            g_partials[task] = v * scale;
            __threadfence();
            int ticket = atomicAdd(&g_count, 1);
            s_last = (ticket == N_TASKS - 1) ? 1 : 0;
        }
    }
    __syncthreads();

    // last block to finish performs the final reduction (fixed order -> deterministic)
    if (s_last) {
        __threadfence();
        float a = 0.0f;
        for (int i = tid; i < N_TASKS; i += NT) a += g_partials[i];
        a = warp_reduce(a);
        if (lane == 0) wsum[wid] = a;
        __syncthreads();
        if (wid == 0) {
            float v = (lane < NT / 32) ? wsum[lane] : 0.0f;
            #pragma unroll
            for (int off = (NT / 32) / 2; off > 0; off >>= 1)
                v += __shfl_down_sync(0xFFFFFFFFu, v, off);
            if (lane == 0) {
                const float f = v + alphas[0] * w[0];   // degree-0 term
                out[0] = 1.0f / (1.0f + expf(-f));
                g_count = 0;                            // reset for graph replay
            }
        }
    }
}

extern "C" void kernel_launch(void* const* d_in, const int* in_sizes, int n_in,
                              void* d_out, int out_size) {
    // metadata order: x [64] f32, w [814385] f32, alphas [5] f32,
    //                 E [814385*64] i32 (UNUSED), ord_ids [814385] i32 (UNUSED)
    const float* x      = (const float*)d_in[0];
    const float* w      = (const float*)d_in[1];
    const float* alphas = (const float*)d_in[2];
    float* out = (float*)d_out;

    poly_fused_kernel<<<N_TASKS, NT>>>(x, w, alphas, out);
}

// round 10
// speedup vs baseline: 1.1789x; 1.1789x over previous
#include <cuda_runtime.h>
#include <cuda_bf16.h>
#include <math.h>

// Monomial layout (D = 64, degrees 0..4):
//   off0=0 (1), off1=1 (64), off2=65 (2080), off3=2145 (45760), off4=47905 (766480)
// Total F = 814385.
//
// Core identity: for fixed leading pair (i,j), the deg-4 inner combos (k,l),
// j<=k<=l<64, enumerate exactly the tail of the full flattened (k,l)-triangle
// starting at S(j) = 64j - j(j-1)/2.  With shared table xx[S(k)+(l-k)] = x_k*x_l
// the inner loop is pure streaming: w[base+p] * xx[S(j)+p].

#define NT 256
#define WARPS_PER_BLOCK (NT / 32)
#define N_M4_TASKS 2080
#define N_TASKS (N_M4_TASKS + 64 + 1 + 1)   // 2146: deg4 pairs + deg3 rows + deg2 + deg1
#define GRID ((N_TASKS + WARPS_PER_BLOCK - 1) / WARPS_PER_BLOCK)   // 269

__device__ float g_partials[GRID];
__device__ int   g_count = 0;

__device__ __forceinline__ int C3i(int n) { return (n >= 3) ? n * (n - 1) * (n - 2) / 6 : 0; }
__device__ __forceinline__ int C4i(int n) { return (n >= 4) ? n * (n - 1) * (n - 2) * (n - 3) / 24 : 0; }
__device__ __forceinline__ int Stri(int k) { return 64 * k - k * (k - 1) / 2; }  // triangle row start

// Unrank p in triangle with rows n, n-1, ..., 1 (once per warp, amortized).
__device__ __forceinline__ void unrank_tri(int n, int p, int& r_out, int& c_out) {
    float b = 2.0f * (float)n + 1.0f;
    int r = (int)(0.5f * (b - sqrtf(b * b - 8.0f * (float)p)));
    if (r < 0) r = 0;
    if (r > n - 1) r = n - 1;
    while (r + 1 <= n - 1 && ((r + 1) * n - (r + 1) * r / 2) <= p) r++;
    while (r > 0 && (r * n - r * (r - 1) / 2) > p) r--;
    r_out = r;
    c_out = p - (r * n - r * (r - 1) / 2);
}

__device__ __forceinline__ float warp_reduce(float v) {
    #pragma unroll
    for (int off = 16; off > 0; off >>= 1)
        v += __shfl_down_sync(0xFFFFFFFFu, v, off);
    return v;
}

__global__ void __launch_bounds__(NT)
poly_stream_kernel(const float* __restrict__ x,
                   const float* __restrict__ w,
                   const float* __restrict__ alphas,
                   float* __restrict__ out) {
    __shared__ float sx[64];
    __shared__ float xx[2080];          // xx[S(k)+(l-k)] = x_k * x_l, k<=l
    __shared__ float sal[5];
    __shared__ float wsum[WARPS_PER_BLOCK];
    __shared__ int   s_last;

    const int tid  = threadIdx.x;
    const int lane = tid & 31;
    const int wid  = tid >> 5;

    if (tid < 64) sx[tid] = x[tid];
    if (tid < 5)  sal[tid] = alphas[tid];
    __syncthreads();

    // Pair table: thread (k = tid>>2, q = tid&3) fills row k with stride 4.
    {
        const int k = tid >> 2;
        const int q = tid & 3;
        const int Sk = Stri(k);
        const float xk = sx[k];
        for (int l = k + q; l < 64; l += 4)
            xx[Sk + (l - k)] = xk * sx[l];
    }
    __syncthreads();

    // ---- one task per warp, STRIPED so each block gets at most one huge task ----
    const int task = blockIdx.x + wid * GRID;
    float result = 0.0f;

    if (task < N_TASKS) {
        int base, xoff, count;
        float scale;

        if (task < N_M4_TASKS) {
            // degree 4: task is the triangle index of leading pair (i,j)
            int i, c;
            unrank_tri(64, task, i, c);
            const int j = i + c;
            base  = 47905 + (C4i(67) - C4i(67 - i)) + (C3i(66 - i) - C3i(66 - j));
            xoff  = Stri(j);
            count = 2080 - xoff;                    // T(64-j)
            scale = sal[4] * sx[i] * sx[j];
        } else if (task < N_M4_TASKS + 64) {
            // degree 3: leading index i
            const int i = task - N_M4_TASKS;
            base  = 2145 + (C3i(66) - C3i(66 - i));
            xoff  = Stri(i);
            count = 2080 - xoff;
            scale = sal[3] * sx[i];
        } else if (task == N_M4_TASKS + 64) {
            base  = 65;  xoff = 0;  count = 2080;  scale = sal[2];
        } else {
            base  = 1;   xoff = -1; count = 64;    scale = sal[1];   // deg-1: use sx
        }

        float acc = 0.0f;
        const float* __restrict__ wp = w + base;
        if (xoff >= 0) {
            const float* __restrict__ xp = xx + xoff;
            int p = lane;
            // 4-deep unrolled stream: maximizes MLP on L2-resident w
            for (; p + 96 < count; p += 128) {
                float a0 = __ldg(wp + p)      * xp[p];
                float a1 = __ldg(wp + p + 32) * xp[p + 32];
                float a2 = __ldg(wp + p + 64) * xp[p + 64];
                float a3 = __ldg(wp + p + 96) * xp[p + 96];
                acc += (a0 + a1) + (a2 + a3);
            }
            for (; p < count; p += 32)
                acc += __ldg(wp + p) * xp[p];
        } else {
            for (int p = lane; p < count; p += 32)
                acc += __ldg(wp + p) * sx[p];
        }

        result = warp_reduce(acc) * scale;
    }

    // block reduction over warps (fixed order -> deterministic)
    if (lane == 0) wsum[wid] = result;
    __syncthreads();
    if (tid == 0) {
        float v = 0.0f;
        #pragma unroll
        for (int i = 0; i < WARPS_PER_BLOCK; i++) v += wsum[i];
        g_partials[blockIdx.x] = v;
        __threadfence();
        int ticket = atomicAdd(&g_count, 1);
        s_last = (ticket == GRID - 1) ? 1 : 0;
    }
    __syncthreads();

    // last block: final deterministic reduction + sigmoid
    if (s_last) {
        __threadfence();
        float a = (tid < GRID) ? g_partials[tid] : 0.0f;
        if (tid + NT < GRID) a += g_partials[tid + NT];
        a = warp_reduce(a);
        if (lane == 0) wsum[wid] = a;
        __syncthreads();
        if (tid == 0) {
            float v = 0.0f;
            #pragma unroll
            for (int i = 0; i < WARPS_PER_BLOCK; i++) v += wsum[i];
            const float f = v + sal[0] * __ldg(w);     // degree-0 term
            out[0] = 1.0f / (1.0f + expf(-f));
            g_count = 0;                               // reset for graph replay
        }
    }
}

extern "C" void kernel_launch(void* const* d_in, const int* in_sizes, int n_in,
                              void* d_out, int out_size) {
    // metadata order: x [64] f32, w [814385] f32, alphas [5] f32,
    //                 E [814385*64] i32 (UNUSED), ord_ids [814385] i32 (UNUSED)
    const float* x      = (const float*)d_in[0];
    const float* w      = (const float*)d_in[1];
    const float* alphas = (const float*)d_in[2];
    float* out = (float*)d_out;

    poly_stream_kernel<<<GRID, NT>>>(x, w, alphas, out);
}

// round 12
// speedup vs baseline: 1.5948x; 1.3528x over previous
#include <cuda_runtime.h>
#include <cuda_bf16.h>
#include <math.h>

// Monomial layout (D = 64, degrees 0..4):
//   off0=0 (1), off1=1 (64), off2=65 (2080), off3=2145 (45760), off4=47905 (766480)
// Total F = 814385.
//
// Core identity: for fixed leading pair (i,j), the deg-4 inner combos (k,l),
// j<=k<=l<64, enumerate exactly the tail of the full flattened (k,l)-triangle
// starting at S(j) = 64j - j(j-1)/2.  With shared table xx[S(k)+(l-k)] = x_k*x_l
// the inner loop is pure streaming: w[base+p] * xx[S(j)+p].

#define NT 256
#define WARPS_PER_BLOCK (NT / 32)
#define N_M4_TASKS 2080
#define N_TASKS (N_M4_TASKS + 64 + 1 + 1)   // 2146: deg4 pairs + deg3 rows + deg2 + deg1
#define GRID ((N_TASKS + WARPS_PER_BLOCK - 1) / WARPS_PER_BLOCK)   // 269

__device__ float g_partials[GRID];
__device__ int   g_count = 0;

__device__ __forceinline__ int C3i(int n) { return (n >= 3) ? n * (n - 1) * (n - 2) / 6 : 0; }
__device__ __forceinline__ int C4i(int n) { return (n >= 4) ? n * (n - 1) * (n - 2) * (n - 3) / 24 : 0; }
__device__ __forceinline__ int Stri(int k) { return 64 * k - k * (k - 1) / 2; }  // triangle row start

// Unrank p in triangle with rows n, n-1, ..., 1 (once per warp, amortized).
__device__ __forceinline__ void unrank_tri(int n, int p, int& r_out, int& c_out) {
    float b = 2.0f * (float)n + 1.0f;
    int r = (int)(0.5f * (b - sqrtf(b * b - 8.0f * (float)p)));
    if (r < 0) r = 0;
    if (r > n - 1) r = n - 1;
    while (r + 1 <= n - 1 && ((r + 1) * n - (r + 1) * r / 2) <= p) r++;
    while (r > 0 && (r * n - r * (r - 1) / 2) > p) r--;
    r_out = r;
    c_out = p - (r * n - r * (r - 1) / 2);
}

__device__ __forceinline__ float warp_reduce(float v) {
    #pragma unroll
    for (int off = 16; off > 0; off >>= 1)
        v += __shfl_down_sync(0xFFFFFFFFu, v, off);
    return v;
}

__global__ void __launch_bounds__(NT)
poly_stream_kernel(const float* __restrict__ x,
                   const float* __restrict__ w,
                   const float* __restrict__ alphas,
                   float* __restrict__ out) {
    __shared__ float sx[64];
    __shared__ float xx[2080];          // xx[S(k)+(l-k)] = x_k * x_l, k<=l
    __shared__ float sal[5];
    __shared__ float wsum[WARPS_PER_BLOCK];
    __shared__ int   s_last;

    const int tid  = threadIdx.x;
    const int lane = tid & 31;
    const int wid  = tid >> 5;

    if (tid < 64) sx[tid] = x[tid];
    if (tid < 5)  sal[tid] = alphas[tid];
    __syncthreads();

    // Pair table: thread (k = tid>>2, q = tid&3) fills row k with stride 4.
    {
        const int k = tid >> 2;
        const int q = tid & 3;
        const int Sk = Stri(k);
        const float xk = sx[k];
        for (int l = k + q; l < 64; l += 4)
            xx[Sk + (l - k)] = xk * sx[l];
    }
    __syncthreads();

    // ---- one task per warp, STRIPED so each block gets at most one huge task ----
    const int task = blockIdx.x + wid * GRID;
    float result = 0.0f;

    if (task < N_TASKS) {
        int base, xoff, count;
        float scale;

        if (task < N_M4_TASKS) {
            // degree 4: task is the triangle index of leading pair (i,j)
            int i, c;
            unrank_tri(64, task, i, c);
            const int j = i + c;
            base  = 47905 + (C4i(67) - C4i(67 - i)) + (C3i(66 - i) - C3i(66 - j));
            xoff  = Stri(j);
            count = 2080 - xoff;                    // T(64-j)
            scale = sal[4] * sx[i] * sx[j];
        } else if (task < N_M4_TASKS + 64) {
            // degree 3: leading index i
            const int i = task - N_M4_TASKS;
            base  = 2145 + (C3i(66) - C3i(66 - i));
            xoff  = Stri(i);
            count = 2080 - xoff;
            scale = sal[3] * sx[i];
        } else if (task == N_M4_TASKS + 64) {
            base  = 65;  xoff = 0;  count = 2080;  scale = sal[2];
        } else {
            base  = 1;   xoff = -1; count = 64;    scale = sal[1];   // deg-1: use sx
        }

        float acc = 0.0f;
        const float* __restrict__ wp = w + base;
        if (xoff >= 0) {
            const float* __restrict__ xp = xx + xoff;
            int p = lane;
            // 8-deep unrolled stream: 8 outstanding LDGs per lane to hide L2 latency
            for (; p + 224 < count; p += 256) {
                float a0 = __ldg(wp + p)       * xp[p];
                float a1 = __ldg(wp + p + 32)  * xp[p + 32];
                float a2 = __ldg(wp + p + 64)  * xp[p + 64];
                float a3 = __ldg(wp + p + 96)  * xp[p + 96];
                float a4 = __ldg(wp + p + 128) * xp[p + 128];
                float a5 = __ldg(wp + p + 160) * xp[p + 160];
                float a6 = __ldg(wp + p + 192) * xp[p + 192];
                float a7 = __ldg(wp + p + 224) * xp[p + 224];
                acc += ((a0 + a1) + (a2 + a3)) + ((a4 + a5) + (a6 + a7));
            }
            for (; p < count; p += 32)
                acc += __ldg(wp + p) * xp[p];
        } else {
            for (int p = lane; p < count; p += 32)
                acc += __ldg(wp + p) * sx[p];
        }

        result = warp_reduce(acc) * scale;
    }

    // block reduction over warps (fixed order -> deterministic)
    if (lane == 0) wsum[wid] = result;
    __syncthreads();
    if (tid == 0) {
        float v = 0.0f;
        #pragma unroll
        for (int i = 0; i < WARPS_PER_BLOCK; i++) v += wsum[i];
        g_partials[blockIdx.x] = v;
        __threadfence();
        int ticket = atomicAdd(&g_count, 1);
        s_last = (ticket == GRID - 1) ? 1 : 0;
    }
    __syncthreads();

    // last block: final deterministic reduction + sigmoid
    if (s_last) {
        __threadfence();
        float a = (tid < GRID) ? g_partials[tid] : 0.0f;
        if (tid + NT < GRID) a += g_partials[tid + NT];
        a = warp_reduce(a);
        if (lane == 0) wsum[wid] = a;
        __syncthreads();
        if (tid == 0) {
            float v = 0.0f;
            #pragma unroll
            for (int i = 0; i < WARPS_PER_BLOCK; i++) v += wsum[i];
            const float f = v + sal[0] * __ldg(w);     // degree-0 term
            out[0] = 1.0f / (1.0f + expf(-f));
            g_count = 0;                               // reset for graph replay
        }
    }
}

extern "C" void kernel_launch(void* const* d_in, const int* in_sizes, int n_in,
                              void* d_out, int out_size) {
    // metadata order: x [64] f32, w [814385] f32, alphas [5] f32,
    //                 E [814385*64] i32 (UNUSED), ord_ids [814385] i32 (UNUSED)
    const float* x      = (const float*)d_in[0];
    const float* w      = (const float*)d_in[1];
    const float* alphas = (const float*)d_in[2];
    float* out = (float*)d_out;

    poly_stream_kernel<<<GRID, NT>>>(x, w, alphas, out);
}